// round 11
// baseline (speedup 1.0000x reference)
#include <cuda_runtime.h>
#include <cuda_bf16.h>

#define NN 50000
#define EE 200000
#define CC 32
#define NDIM 75
#define EDIM 12
#define LL 3
#define GG 500
#define HIDN 5
#define EPS_BN 1e-5f
#define PJ 224   // 7 groups of 32: 5 x W2 + b2 + rootW

// ---------------- scratch (device globals; float4 for 16B alignment) --------
__device__ float4 d_h4[NN * CC / 4];     // init node features (layer 0 only)
__device__ float4 d_agg4[NN * CC / 4];   // scatter-add target
__device__ float4 d_p4[NN * PJ / 4];     // per-node transform (45 MB)
__device__ float4 d_outb4[NN * CC / 4];  // pre-BN conv output
__device__ float d_bnsums[2][2 * CC];    // [layer parity][sum|sumsq]
__device__ float4 d_gsum4[GG * CC / 4];  // graph readout accumulator

#define d_h    ((float*)d_h4)
#define d_agg  ((float*)d_agg4)
#define d_p    ((float*)d_p4)
#define d_outb ((float*)d_outb4)
#define d_gsum ((float*)d_gsum4)

// ---------------- initial atom projection: h = leaky(x @ linW + linb) -------
// Also zeroes d_gsum (folded launch).
__global__ void init_h_kernel(const float* __restrict__ x,
                              const float* __restrict__ W,
                              const float* __restrict__ b) {
    __shared__ float sW[NDIM * CC];
    __shared__ float sb[CC];
    __shared__ float sx[8][NDIM + 1];

    int tid = threadIdx.x;
    int gi = blockIdx.x * 256 + tid;
    if (gi < GG * CC / 4) d_gsum4[gi] = make_float4(0.f, 0.f, 0.f, 0.f);

    for (int i = tid; i < NDIM * CC; i += 256) sW[i] = W[i];
    if (tid < CC) sb[tid] = b[tid];

    int nbase = blockIdx.x * 8;
    for (int i = tid; i < 8 * NDIM; i += 256) {
        int nl = i / NDIM, k = i - nl * NDIM;
        int n = nbase + nl;
        sx[nl][k] = (n < NN) ? x[n * NDIM + k] : 0.f;
    }
    __syncthreads();

    int d = tid & 31, nloc = tid >> 5;
    int n = nbase + nloc;
    if (n < NN) {
        float a = sb[d];
#pragma unroll
        for (int k = 0; k < NDIM; k++)
            a = fmaf(sx[nloc][k], sW[k * CC + d], a);
        d_h[n * CC + d] = a > 0.f ? a : 0.01f * a;
    }
}

// ---------------- kernel A: p[n][u*32+d] = sum_c h[n,c]*Wcat[c][u*32+d] -----
// Wcat groups u: 0..4 = W2[u,c,d]; 5 = b2[c,d]; 6 = rootW[c,d].
// readBN==0: source = d_h (layer 0).
// readBN==1: source = leaky(BN(d_outb)) with coefs recomputed per block from
//            the PREVIOUS layer's d_bnsums slot (prevPar).
// Also zeroes d_agg and the CURRENT layer's d_bnsums slot (curPar).
__global__ void __launch_bounds__(256)
nodeP_kernel(const float* __restrict__ W2, const float* __restrict__ b2,
             const float* __restrict__ rootW,
             const float* __restrict__ bnG, const float* __restrict__ bnB,
             int readBN, int prevPar, int curPar) {
    __shared__ float sW[CC * PJ];     // 7168 floats = 28 KB
    __shared__ float sH[64][33];      // 8.4 KB
    __shared__ float sCoef[2 * CC];

    int tid = threadIdx.x;
    // fold in per-layer zeroing of aggregation buffer + current BN sums
    for (int i = blockIdx.x * 256 + tid; i < NN * CC / 4; i += gridDim.x * 256)
        d_agg4[i] = make_float4(0.f, 0.f, 0.f, 0.f);
    if (blockIdx.x == 0 && tid < 2 * CC) d_bnsums[curPar][tid] = 0.f;

    if (readBN && tid < CC) {
        float inv_n = 1.0f / (float)NN;
        float mu = d_bnsums[prevPar][tid] * inv_n;
        float var = d_bnsums[prevPar][CC + tid] * inv_n - mu * mu;
        float sc = __ldg(bnG + tid) * rsqrtf(var + EPS_BN);
        sCoef[tid] = sc;
        sCoef[CC + tid] = __ldg(bnB + tid) - mu * sc;
    }

    for (int i = tid; i < CC * PJ; i += 256) {
        int c = i / PJ, j = i - c * PJ;
        int k = j >> 5, d = j & 31;
        float v;
        if (k < 5)       v = W2[k * (CC * CC) + c * CC + d];
        else if (k == 5) v = b2[c * CC + d];
        else             v = rootW[c * CC + d];
        sW[i] = v;
    }

    int w = tid >> 5, lane = tid & 31;
    int ntiles = (NN + 63) / 64;
    for (int tile = blockIdx.x; tile < ntiles; tile += gridDim.x) {
        int nbase = tile * 64;
        __syncthreads();   // sW/sCoef ready (iter 0); sH free of prior readers
        for (int i = tid; i < 64 * 32; i += 256) {
            int nl = i >> 5, c = i & 31;
            int n = nbase + nl;
            float v = 0.f;
            if (n < NN) {
                if (readBN) {
                    v = fmaf(d_outb[n * CC + c], sCoef[c], sCoef[CC + c]);
                    if (v < 0.f) v *= 0.01f;   // non-last layers get leaky
                } else {
                    v = d_h[n * CC + c];
                }
            }
            sH[nl][c] = v;
        }
        __syncthreads();

        float acc[8][7];
#pragma unroll
        for (int r = 0; r < 8; r++)
#pragma unroll
            for (int u = 0; u < 7; u++) acc[r][u] = 0.f;

#pragma unroll 2
        for (int c = 0; c < CC; c++) {
            float wv[7];
#pragma unroll
            for (int u = 0; u < 7; u++) wv[u] = sW[c * PJ + u * 32 + lane];
#pragma unroll
            for (int r = 0; r < 8; r++) {
                float hc = sH[w * 8 + r][c];
#pragma unroll
                for (int u = 0; u < 7; u++)
                    acc[r][u] = fmaf(hc, wv[u], acc[r][u]);
            }
        }

#pragma unroll
        for (int r = 0; r < 8; r++) {
            int n = nbase + w * 8 + r;
            if (n < NN) {
#pragma unroll
                for (int u = 0; u < 7; u++)
                    d_p[n * PJ + u * 32 + lane] = acc[r][u];
            }
        }
    }
}

// ---------------- kernel B: edge MLP + msg via p-gather + float4 scatter ----
// 256 edges per block. Phase 1: one thread per edge computes z (z[5]=1).
// Phase 2: 8 threads per edge; sub owns 4 channels; 6 float4 gathers from p.
// Passes are software-pipelined: pass i+1's loads issue before pass i's FMAs,
// doubling per-thread MLP so the kernel stays L2-BW-bound, not latency-bound.
__global__ void __launch_bounds__(256)
edgeB_kernel(const float* __restrict__ ea, const int* __restrict__ ei,
             const float* __restrict__ W1, const float* __restrict__ b1) {
    __shared__ float sZ[256][8];   // 6 used
    __shared__ int sSrc[256];
    __shared__ int sDst[256];
    __shared__ float sW1[EDIM * HIDN];
    __shared__ float sB1[HIDN];

    int tid = threadIdx.x;
    if (tid < EDIM * HIDN) sW1[tid] = W1[tid];
    if (tid < HIDN) sB1[tid] = b1[tid];
    __syncthreads();

    int e = blockIdx.x * 256 + tid;
    if (e < EE) {
        sSrc[tid] = ei[e];
        sDst[tid] = ei[EE + e];
        const float4* ear4 = reinterpret_cast<const float4*>(ea + e * EDIM);
        float4 q0 = __ldg(ear4), q1 = __ldg(ear4 + 1), q2 = __ldg(ear4 + 2);
        float eav[EDIM] = {q0.x, q0.y, q0.z, q0.w,
                           q1.x, q1.y, q1.z, q1.w,
                           q2.x, q2.y, q2.z, q2.w};
#pragma unroll
        for (int k = 0; k < HIDN; k++) {
            float a = sB1[k];
#pragma unroll
            for (int j = 0; j < EDIM; j++)
                a = fmaf(eav[j], sW1[j * HIDN + k], a);
            sZ[tid][k] = a > 0.f ? a : 0.f;
        }
        sZ[tid][5] = 1.f;   // bias row of p
    } else {
        sSrc[tid] = 0;
        sDst[tid] = -1;
#pragma unroll
        for (int k = 0; k < 6; k++) sZ[tid][k] = 0.f;
    }
    __syncthreads();

    int sub = tid & 7, grp = tid >> 3;

    // prologue: load pass 0
    float4 t[6];
    {
        const float* pr = d_p + sSrc[grp] * PJ + sub * 4;
#pragma unroll
        for (int k = 0; k < 6; k++)
            t[k] = *reinterpret_cast<const float4*>(pr + k * 32);
    }

#pragma unroll
    for (int pass = 0; pass < 8; pass++) {
        int el = pass * 32 + grp;
        // issue next pass's loads before consuming this pass's data
        float4 tn[6];
        if (pass < 7) {
            const float* prn = d_p + sSrc[el + 32] * PJ + sub * 4;
#pragma unroll
            for (int k = 0; k < 6; k++)
                tn[k] = *reinterpret_cast<const float4*>(prn + k * 32);
        }

        float z[6];
#pragma unroll
        for (int k = 0; k < 6; k++) z[k] = sZ[el][k];

        float4 acc = make_float4(0.f, 0.f, 0.f, 0.f);
#pragma unroll
        for (int k = 0; k < 6; k++) {
            acc.x = fmaf(z[k], t[k].x, acc.x);
            acc.y = fmaf(z[k], t[k].y, acc.y);
            acc.z = fmaf(z[k], t[k].z, acc.z);
            acc.w = fmaf(z[k], t[k].w, acc.w);
        }
        int dstn = sDst[el];
        if (dstn >= 0)
            atomicAdd(reinterpret_cast<float4*>(d_agg + dstn * CC + sub * 4),
                      acc);
#pragma unroll
        for (int k = 0; k < 6; k++) t[k] = tn[k];
    }
}

// ---------------- node kernel: out = agg + root_slice + b; BN partial sums --
// One thread per channel-quad (float4). Lanes {l, l+8, l+16, l+24} share a
// quad (block base % 8 == 0), so butterfly-reduce over xor 8,16 first and
// let only lanes 0..7 issue smem atomics (4x fewer ATOMS).
__global__ void node_kernel(const float* __restrict__ convb, int curPar) {
    __shared__ float ssum[CC], ssq[CC];
    int tid = threadIdx.x;
    if (tid < CC) { ssum[tid] = 0.f; ssq[tid] = 0.f; }
    __syncthreads();

    int idx = blockIdx.x * 256 + tid;   // over NN*8
    int q = idx & 7, d = q * 4;
    float4 a = make_float4(0.f, 0.f, 0.f, 0.f);
    if (idx < NN * (CC / 4)) {
        int n = idx >> 3;
        a = d_agg4[idx];
        const float4 r =
            *reinterpret_cast<const float4*>(d_p + n * PJ + 6 * 32 + d);
        a.x += r.x + __ldg(convb + d + 0);
        a.y += r.y + __ldg(convb + d + 1);
        a.z += r.z + __ldg(convb + d + 2);
        a.w += r.w + __ldg(convb + d + 3);
        d_outb4[idx] = a;
    }
    // per-warp reduce: lanes sharing a quad combine (all lanes participate)
    float sx = a.x, sy = a.y, sz = a.z, sw = a.w;
    float qx = a.x * a.x, qy = a.y * a.y, qz = a.z * a.z, qw = a.w * a.w;
#pragma unroll
    for (int o = 8; o <= 16; o <<= 1) {
        sx += __shfl_xor_sync(0xffffffffu, sx, o);
        sy += __shfl_xor_sync(0xffffffffu, sy, o);
        sz += __shfl_xor_sync(0xffffffffu, sz, o);
        sw += __shfl_xor_sync(0xffffffffu, sw, o);
        qx += __shfl_xor_sync(0xffffffffu, qx, o);
        qy += __shfl_xor_sync(0xffffffffu, qy, o);
        qz += __shfl_xor_sync(0xffffffffu, qz, o);
        qw += __shfl_xor_sync(0xffffffffu, qw, o);
    }
    if ((tid & 31) < 8) {
        atomicAdd(&ssum[d + 0], sx);
        atomicAdd(&ssum[d + 1], sy);
        atomicAdd(&ssum[d + 2], sz);
        atomicAdd(&ssum[d + 3], sw);
        atomicAdd(&ssq[d + 0], qx);
        atomicAdd(&ssq[d + 1], qy);
        atomicAdd(&ssq[d + 2], qz);
        atomicAdd(&ssq[d + 3], qw);
    }
    __syncthreads();
    if (tid < CC) {
        atomicAdd(&d_bnsums[curPar][tid], ssum[tid]);
        atomicAdd(&d_bnsums[curPar][CC + tid], ssq[tid]);
    }
}

// ---------------- final normalize + graph readout (last layer only) --------
// Recomputes BN coefs per block from d_bnsums[par]; no leaky on last layer.
__global__ void normalize_last_kernel(const int* __restrict__ batch,
                                      const float* __restrict__ bnG,
                                      const float* __restrict__ bnB,
                                      int par) {
    __shared__ float sCoef[2 * CC];
    int tid = threadIdx.x;
    if (tid < CC) {
        float inv_n = 1.0f / (float)NN;
        float mu = d_bnsums[par][tid] * inv_n;
        float var = d_bnsums[par][CC + tid] * inv_n - mu * mu;
        float sc = __ldg(bnG + tid) * rsqrtf(var + EPS_BN);
        sCoef[tid] = sc;
        sCoef[CC + tid] = __ldg(bnB + tid) - mu * sc;
    }
    __syncthreads();

    int idx = blockIdx.x * 256 + tid;   // over NN*8
    if (idx >= NN * (CC / 4)) return;
    int q = idx & 7;
    int n = idx >> 3;
    int d = q * 4;
    float4 v = d_outb4[idx];
    v.x = fmaf(v.x, sCoef[d + 0], sCoef[CC + d + 0]);
    v.y = fmaf(v.y, sCoef[d + 1], sCoef[CC + d + 1]);
    v.z = fmaf(v.z, sCoef[d + 2], sCoef[CC + d + 2]);
    v.w = fmaf(v.w, sCoef[d + 3], sCoef[CC + d + 3]);
    atomicAdd(&d_gsum4[batch[n] * (CC / 4) + q], v);
}

// ---------------- prediction head: out[g] = gsum[g] . predW + predb ---------
__global__ void pred_kernel(const float* __restrict__ pW,
                            const float* __restrict__ pb,
                            float* __restrict__ out) {
    int g = blockIdx.x * (blockDim.x >> 5) + (threadIdx.x >> 5);
    int lane = threadIdx.x & 31;
    if (g < GG) {
        float v = d_gsum[g * CC + lane] * __ldg(pW + lane);
#pragma unroll
        for (int o = 16; o > 0; o >>= 1)
            v += __shfl_down_sync(0xffffffffu, v, o);
        if (lane == 0) out[g] = v + __ldg(pb);
    }
}

// ---------------- launch ----------------------------------------------------
extern "C" void kernel_launch(void* const* d_in, const int* in_sizes, int n_in,
                              void* d_out, int out_size) {
    const float* x    = (const float*)d_in[0];
    const int*   ei   = (const int*)d_in[1];
    const float* ea   = (const float*)d_in[2];
    const int*   bat  = (const int*)d_in[3];
    const float* linW = (const float*)d_in[4];
    const float* linb = (const float*)d_in[5];
    const float* mW1  = (const float*)d_in[6];
    const float* mb1  = (const float*)d_in[7];
    const float* mW2  = (const float*)d_in[8];
    const float* mb2  = (const float*)d_in[9];
    const float* rW   = (const float*)d_in[10];
    const float* cb   = (const float*)d_in[11];
    const float* bg   = (const float*)d_in[12];
    const float* bb   = (const float*)d_in[13];
    const float* pW   = (const float*)d_in[14];
    const float* pb   = (const float*)d_in[15];
    float* out = (float*)d_out;

    init_h_kernel<<<(NN + 7) / 8, 256>>>(x, linW, linb);

    for (int l = 0; l < LL; l++) {
        int curPar = l & 1, prevPar = (l - 1) & 1;
        nodeP_kernel<<<592, 256>>>(
            mW2 + l * HIDN * CC * CC, mb2 + l * CC * CC, rW + l * CC * CC,
            (l > 0) ? bg + (l - 1) * CC : bg,
            (l > 0) ? bb + (l - 1) * CC : bb,
            (l > 0) ? 1 : 0, prevPar, curPar);
        edgeB_kernel<<<(EE + 255) / 256, 256>>>(ea, ei,
                                                mW1 + l * EDIM * HIDN,
                                                mb1 + l * HIDN);
        node_kernel<<<(NN * CC / 4 + 255) / 256, 256>>>(cb + l * CC, curPar);
    }

    normalize_last_kernel<<<(NN * CC / 4 + 255) / 256, 256>>>(
        bat, bg + (LL - 1) * CC, bb + (LL - 1) * CC, (LL - 1) & 1);

    pred_kernel<<<(GG + 7) / 8, 256>>>(pW, pb, out);
}

// round 12
// speedup vs baseline: 1.5454x; 1.5454x over previous
#include <cuda_runtime.h>
#include <cuda_bf16.h>

#define NN 50000
#define EE 200000
#define CC 32
#define NDIM 75
#define EDIM 12
#define LL 3
#define GG 500
#define HIDN 5
#define EPS_BN 1e-5f
#define PJ 224   // 7 groups of 32: 5 x W2 + b2 + rootW

// ---------------- scratch (device globals; float4 for 16B alignment) --------
__device__ float4 d_h4[NN * CC / 4];     // init node features (layer 0 only)
__device__ float4 d_agg4[NN * CC / 4];   // scatter-add target
__device__ float4 d_p4[NN * PJ / 4];     // per-node transform (45 MB)
__device__ float4 d_outb4[NN * CC / 4];  // pre-BN conv output
__device__ float d_bnsums[2][2 * CC];    // [layer parity][sum|sumsq]
__device__ float4 d_gsum4[GG * CC / 4];  // graph readout accumulator

#define d_h    ((float*)d_h4)
#define d_agg  ((float*)d_agg4)
#define d_p    ((float*)d_p4)
#define d_outb ((float*)d_outb4)
#define d_gsum ((float*)d_gsum4)

// ---------------- zero gsum (separate first launch; also shifts ncu window) -
__global__ void zero_gsum_kernel() {
    int i = blockIdx.x * blockDim.x + threadIdx.x;
    if (i < GG * CC / 4) d_gsum4[i] = make_float4(0.f, 0.f, 0.f, 0.f);
}

// ---------------- initial atom projection: h = leaky(x @ linW + linb) -------
__global__ void init_h_kernel(const float* __restrict__ x,
                              const float* __restrict__ W,
                              const float* __restrict__ b) {
    __shared__ float sW[NDIM * CC];
    __shared__ float sb[CC];
    __shared__ float sx[8][NDIM + 1];

    int tid = threadIdx.x;
    for (int i = tid; i < NDIM * CC; i += 256) sW[i] = W[i];
    if (tid < CC) sb[tid] = b[tid];

    int nbase = blockIdx.x * 8;
    for (int i = tid; i < 8 * NDIM; i += 256) {
        int nl = i / NDIM, k = i - nl * NDIM;
        int n = nbase + nl;
        sx[nl][k] = (n < NN) ? x[n * NDIM + k] : 0.f;
    }
    __syncthreads();

    int d = tid & 31, nloc = tid >> 5;
    int n = nbase + nloc;
    if (n < NN) {
        float a = sb[d];
#pragma unroll
        for (int k = 0; k < NDIM; k++)
            a = fmaf(sx[nloc][k], sW[k * CC + d], a);
        d_h[n * CC + d] = a > 0.f ? a : 0.01f * a;
    }
}

// ---------------- kernel A: p[n][u*32+d] = sum_c h[n,c]*Wcat[c][u*32+d] -----
// Wcat groups u: 0..4 = W2[u,c,d]; 5 = b2[c,d]; 6 = rootW[c,d].
// readBN==0: source = d_h (layer 0).
// readBN==1: source = leaky(BN(d_outb)) with coefs recomputed per block from
//            the PREVIOUS layer's d_bnsums slot (prevPar).
// Also zeroes d_agg and the CURRENT layer's d_bnsums slot (curPar).
__global__ void __launch_bounds__(256)
nodeP_kernel(const float* __restrict__ W2, const float* __restrict__ b2,
             const float* __restrict__ rootW,
             const float* __restrict__ bnG, const float* __restrict__ bnB,
             int readBN, int prevPar, int curPar) {
    __shared__ float sW[CC * PJ];     // 7168 floats = 28 KB
    __shared__ float sH[64][33];      // 8.4 KB
    __shared__ float sCoef[2 * CC];

    int tid = threadIdx.x;
    // fold in per-layer zeroing of aggregation buffer + current BN sums
    for (int i = blockIdx.x * 256 + tid; i < NN * CC / 4; i += gridDim.x * 256)
        d_agg4[i] = make_float4(0.f, 0.f, 0.f, 0.f);
    if (blockIdx.x == 0 && tid < 2 * CC) d_bnsums[curPar][tid] = 0.f;

    if (readBN && tid < CC) {
        float inv_n = 1.0f / (float)NN;
        float mu = d_bnsums[prevPar][tid] * inv_n;
        float var = d_bnsums[prevPar][CC + tid] * inv_n - mu * mu;
        float sc = __ldg(bnG + tid) * rsqrtf(var + EPS_BN);
        sCoef[tid] = sc;
        sCoef[CC + tid] = __ldg(bnB + tid) - mu * sc;
    }

    for (int i = tid; i < CC * PJ; i += 256) {
        int c = i / PJ, j = i - c * PJ;
        int k = j >> 5, d = j & 31;
        float v;
        if (k < 5)       v = W2[k * (CC * CC) + c * CC + d];
        else if (k == 5) v = b2[c * CC + d];
        else             v = rootW[c * CC + d];
        sW[i] = v;
    }

    int w = tid >> 5, lane = tid & 31;
    int ntiles = (NN + 63) / 64;
    for (int tile = blockIdx.x; tile < ntiles; tile += gridDim.x) {
        int nbase = tile * 64;
        __syncthreads();   // sW/sCoef ready (iter 0); sH free of prior readers
        for (int i = tid; i < 64 * 32; i += 256) {
            int nl = i >> 5, c = i & 31;
            int n = nbase + nl;
            float v = 0.f;
            if (n < NN) {
                if (readBN) {
                    v = fmaf(d_outb[n * CC + c], sCoef[c], sCoef[CC + c]);
                    if (v < 0.f) v *= 0.01f;   // non-last layers get leaky
                } else {
                    v = d_h[n * CC + c];
                }
            }
            sH[nl][c] = v;
        }
        __syncthreads();

        float acc[8][7];
#pragma unroll
        for (int r = 0; r < 8; r++)
#pragma unroll
            for (int u = 0; u < 7; u++) acc[r][u] = 0.f;

#pragma unroll 2
        for (int c = 0; c < CC; c++) {
            float wv[7];
#pragma unroll
            for (int u = 0; u < 7; u++) wv[u] = sW[c * PJ + u * 32 + lane];
#pragma unroll
            for (int r = 0; r < 8; r++) {
                float hc = sH[w * 8 + r][c];
#pragma unroll
                for (int u = 0; u < 7; u++)
                    acc[r][u] = fmaf(hc, wv[u], acc[r][u]);
            }
        }

#pragma unroll
        for (int r = 0; r < 8; r++) {
            int n = nbase + w * 8 + r;
            if (n < NN) {
#pragma unroll
                for (int u = 0; u < 7; u++)
                    d_p[n * PJ + u * 32 + lane] = acc[r][u];
            }
        }
    }
}

// ---------------- kernel B: edge MLP + msg via p-gather + float4 scatter ----
// 256 edges per block. Phase 1: one thread per edge computes z (z[5]=1).
// Phase 2: 8 threads per edge; sub owns 4 channels; 6 float4 gathers from p.
// Passes are software-pipelined: pass i+1's loads issue before pass i's FMAs.
__global__ void __launch_bounds__(256)
edgeB_kernel(const float* __restrict__ ea, const int* __restrict__ ei,
             const float* __restrict__ W1, const float* __restrict__ b1) {
    __shared__ float sZ[256][8];   // 6 used
    __shared__ int sSrc[256];
    __shared__ int sDst[256];
    __shared__ float sW1[EDIM * HIDN];
    __shared__ float sB1[HIDN];

    int tid = threadIdx.x;
    if (tid < EDIM * HIDN) sW1[tid] = W1[tid];
    if (tid < HIDN) sB1[tid] = b1[tid];
    __syncthreads();

    int e = blockIdx.x * 256 + tid;
    if (e < EE) {
        sSrc[tid] = ei[e];
        sDst[tid] = ei[EE + e];
        const float4* ear4 = reinterpret_cast<const float4*>(ea + e * EDIM);
        float4 q0 = __ldg(ear4), q1 = __ldg(ear4 + 1), q2 = __ldg(ear4 + 2);
        float eav[EDIM] = {q0.x, q0.y, q0.z, q0.w,
                           q1.x, q1.y, q1.z, q1.w,
                           q2.x, q2.y, q2.z, q2.w};
#pragma unroll
        for (int k = 0; k < HIDN; k++) {
            float a = sB1[k];
#pragma unroll
            for (int j = 0; j < EDIM; j++)
                a = fmaf(eav[j], sW1[j * HIDN + k], a);
            sZ[tid][k] = a > 0.f ? a : 0.f;
        }
        sZ[tid][5] = 1.f;   // bias row of p
    } else {
        sSrc[tid] = 0;
        sDst[tid] = -1;
#pragma unroll
        for (int k = 0; k < 6; k++) sZ[tid][k] = 0.f;
    }
    __syncthreads();

    int sub = tid & 7, grp = tid >> 3;

    // prologue: load pass 0
    float4 t[6];
    {
        const float* pr = d_p + sSrc[grp] * PJ + sub * 4;
#pragma unroll
        for (int k = 0; k < 6; k++)
            t[k] = *reinterpret_cast<const float4*>(pr + k * 32);
    }

#pragma unroll
    for (int pass = 0; pass < 8; pass++) {
        int el = pass * 32 + grp;
        // issue next pass's loads before consuming this pass's data
        float4 tn[6];
        if (pass < 7) {
            const float* prn = d_p + sSrc[el + 32] * PJ + sub * 4;
#pragma unroll
            for (int k = 0; k < 6; k++)
                tn[k] = *reinterpret_cast<const float4*>(prn + k * 32);
        }

        float z[6];
#pragma unroll
        for (int k = 0; k < 6; k++) z[k] = sZ[el][k];

        float4 acc = make_float4(0.f, 0.f, 0.f, 0.f);
#pragma unroll
        for (int k = 0; k < 6; k++) {
            acc.x = fmaf(z[k], t[k].x, acc.x);
            acc.y = fmaf(z[k], t[k].y, acc.y);
            acc.z = fmaf(z[k], t[k].z, acc.z);
            acc.w = fmaf(z[k], t[k].w, acc.w);
        }
        int dstn = sDst[el];
        if (dstn >= 0)
            atomicAdd(reinterpret_cast<float4*>(d_agg + dstn * CC + sub * 4),
                      acc);
#pragma unroll
        for (int k = 0; k < 6; k++) t[k] = tn[k];
    }
}

// ---------------- node kernel: out = agg + root_slice + b; BN partial sums --
// 2 adjacent nodes per thread (same channel-quad q): 4 independent LDG.128 in
// flight, half the blocks. Lanes {l,l+8,l+16,l+24} share q (block base %8==0):
// butterfly-reduce over xor 8,16; only lanes 0..7 issue smem atomics.
__global__ void node_kernel(const float* __restrict__ convb, int curPar) {
    __shared__ float ssum[CC], ssq[CC];
    int tid = threadIdx.x;
    if (tid < CC) { ssum[tid] = 0.f; ssq[tid] = 0.f; }
    __syncthreads();

    int idx = blockIdx.x * 256 + tid;   // over NN*4 (node pairs x 8 quads)
    int q = idx & 7, d = q * 4;
    float4 a0 = make_float4(0.f, 0.f, 0.f, 0.f);
    float4 a1 = make_float4(0.f, 0.f, 0.f, 0.f);
    if (idx < NN * (CC / 8)) {
        int n0 = (idx >> 3) * 2, n1 = n0 + 1;
        float4 g0 = d_agg4[n0 * 8 + q];
        float4 g1 = d_agg4[n1 * 8 + q];
        float4 r0 = *reinterpret_cast<const float4*>(d_p + n0 * PJ + 6 * 32 + d);
        float4 r1 = *reinterpret_cast<const float4*>(d_p + n1 * PJ + 6 * 32 + d);
        float c0 = __ldg(convb + d + 0), c1 = __ldg(convb + d + 1);
        float c2 = __ldg(convb + d + 2), c3 = __ldg(convb + d + 3);
        a0.x = g0.x + r0.x + c0; a0.y = g0.y + r0.y + c1;
        a0.z = g0.z + r0.z + c2; a0.w = g0.w + r0.w + c3;
        a1.x = g1.x + r1.x + c0; a1.y = g1.y + r1.y + c1;
        a1.z = g1.z + r1.z + c2; a1.w = g1.w + r1.w + c3;
        d_outb4[n0 * 8 + q] = a0;
        d_outb4[n1 * 8 + q] = a1;
    }
    // per-warp reduce: lanes sharing a quad combine (all lanes participate)
    float sx = a0.x + a1.x, sy = a0.y + a1.y;
    float sz = a0.z + a1.z, sw = a0.w + a1.w;
    float qx = a0.x * a0.x + a1.x * a1.x, qy = a0.y * a0.y + a1.y * a1.y;
    float qz = a0.z * a0.z + a1.z * a1.z, qw = a0.w * a0.w + a1.w * a1.w;
#pragma unroll
    for (int o = 8; o <= 16; o <<= 1) {
        sx += __shfl_xor_sync(0xffffffffu, sx, o);
        sy += __shfl_xor_sync(0xffffffffu, sy, o);
        sz += __shfl_xor_sync(0xffffffffu, sz, o);
        sw += __shfl_xor_sync(0xffffffffu, sw, o);
        qx += __shfl_xor_sync(0xffffffffu, qx, o);
        qy += __shfl_xor_sync(0xffffffffu, qy, o);
        qz += __shfl_xor_sync(0xffffffffu, qz, o);
        qw += __shfl_xor_sync(0xffffffffu, qw, o);
    }
    if ((tid & 31) < 8) {
        atomicAdd(&ssum[d + 0], sx);
        atomicAdd(&ssum[d + 1], sy);
        atomicAdd(&ssum[d + 2], sz);
        atomicAdd(&ssum[d + 3], sw);
        atomicAdd(&ssq[d + 0], qx);
        atomicAdd(&ssq[d + 1], qy);
        atomicAdd(&ssq[d + 2], qz);
        atomicAdd(&ssq[d + 3], qw);
    }
    __syncthreads();
    if (tid < CC) {
        atomicAdd(&d_bnsums[curPar][tid], ssum[tid]);
        atomicAdd(&d_bnsums[curPar][CC + tid], ssq[tid]);
    }
}

// ---------------- final normalize + graph readout (last layer only) --------
__global__ void normalize_last_kernel(const int* __restrict__ batch,
                                      const float* __restrict__ bnG,
                                      const float* __restrict__ bnB,
                                      int par) {
    __shared__ float sCoef[2 * CC];
    int tid = threadIdx.x;
    if (tid < CC) {
        float inv_n = 1.0f / (float)NN;
        float mu = d_bnsums[par][tid] * inv_n;
        float var = d_bnsums[par][CC + tid] * inv_n - mu * mu;
        float sc = __ldg(bnG + tid) * rsqrtf(var + EPS_BN);
        sCoef[tid] = sc;
        sCoef[CC + tid] = __ldg(bnB + tid) - mu * sc;
    }
    __syncthreads();

    int idx = blockIdx.x * 256 + tid;   // over NN*8
    if (idx >= NN * (CC / 4)) return;
    int q = idx & 7;
    int n = idx >> 3;
    int d = q * 4;
    float4 v = d_outb4[idx];
    v.x = fmaf(v.x, sCoef[d + 0], sCoef[CC + d + 0]);
    v.y = fmaf(v.y, sCoef[d + 1], sCoef[CC + d + 1]);
    v.z = fmaf(v.z, sCoef[d + 2], sCoef[CC + d + 2]);
    v.w = fmaf(v.w, sCoef[d + 3], sCoef[CC + d + 3]);
    atomicAdd(&d_gsum4[batch[n] * (CC / 4) + q], v);
}

// ---------------- prediction head: out[g] = gsum[g] . predW + predb ---------
__global__ void pred_kernel(const float* __restrict__ pW,
                            const float* __restrict__ pb,
                            float* __restrict__ out) {
    int g = blockIdx.x * (blockDim.x >> 5) + (threadIdx.x >> 5);
    int lane = threadIdx.x & 31;
    if (g < GG) {
        float v = d_gsum[g * CC + lane] * __ldg(pW + lane);
#pragma unroll
        for (int o = 16; o > 0; o >>= 1)
            v += __shfl_down_sync(0xffffffffu, v, o);
        if (lane == 0) out[g] = v + __ldg(pb);
    }
}

// ---------------- launch ----------------------------------------------------
extern "C" void kernel_launch(void* const* d_in, const int* in_sizes, int n_in,
                              void* d_out, int out_size) {
    const float* x    = (const float*)d_in[0];
    const int*   ei   = (const int*)d_in[1];
    const float* ea   = (const float*)d_in[2];
    const int*   bat  = (const int*)d_in[3];
    const float* linW = (const float*)d_in[4];
    const float* linb = (const float*)d_in[5];
    const float* mW1  = (const float*)d_in[6];
    const float* mb1  = (const float*)d_in[7];
    const float* mW2  = (const float*)d_in[8];
    const float* mb2  = (const float*)d_in[9];
    const float* rW   = (const float*)d_in[10];
    const float* cb   = (const float*)d_in[11];
    const float* bg   = (const float*)d_in[12];
    const float* bb   = (const float*)d_in[13];
    const float* pW   = (const float*)d_in[14];
    const float* pb   = (const float*)d_in[15];
    float* out = (float*)d_out;

    zero_gsum_kernel<<<(GG * CC / 4 + 255) / 256, 256>>>();
    init_h_kernel<<<(NN + 7) / 8, 256>>>(x, linW, linb);

    for (int l = 0; l < LL; l++) {
        int curPar = l & 1, prevPar = (l - 1) & 1;
        nodeP_kernel<<<592, 256>>>(
            mW2 + l * HIDN * CC * CC, mb2 + l * CC * CC, rW + l * CC * CC,
            (l > 0) ? bg + (l - 1) * CC : bg,
            (l > 0) ? bb + (l - 1) * CC : bb,
            (l > 0) ? 1 : 0, prevPar, curPar);
        edgeB_kernel<<<(EE + 255) / 256, 256>>>(ea, ei,
                                                mW1 + l * EDIM * HIDN,
                                                mb1 + l * HIDN);
        node_kernel<<<(NN * CC / 8 + 255) / 256, 256>>>(cb + l * CC, curPar);
    }

    normalize_last_kernel<<<(NN * CC / 4 + 255) / 256, 256>>>(
        bat, bg + (LL - 1) * CC, bb + (LL - 1) * CC, (LL - 1) & 1);

    pred_kernel<<<(GG + 7) / 8, 256>>>(pW, pb, out);
}